// round 6
// baseline (speedup 1.0000x reference)
#include <cuda_runtime.h>
#include <cstdint>

#define BB 16
#define NN 4096
#define DD 1024
#define HH 16
#define DKK 64
#define CBLK 9            // row-chunks per batch -> 144 blocks ~= 1 wave
#define CROWS 464         // rows per chunk (c<8); last chunk gets 384
#define TR 16             // tile rows

typedef unsigned long long u64;

// ---- scratch (static __device__ — no allocation allowed) ----
__device__ float g_qk[HH * DD];                          // folded (log2e/SCALE) * Q@Wk_head
__device__ float g_ps[(size_t)BB * CBLK * HH * DD];      // partial weighted sums
__device__ float g_pz[BB * CBLK * HH];                   // partial softmax denominators
__device__ float g_s[(size_t)BB * HH * DD];              // normalized weighted avg of x
__device__ float g_pooled[BB * DD];                      // per-head Wv matvec results

// ---- packed f32x2 helpers ----
__device__ __forceinline__ u64 ffma2(u64 a, u64 b, u64 c) {
    u64 d;
    asm("fma.rn.f32x2 %0, %1, %2, %3;" : "=l"(d) : "l"(a), "l"(b), "l"(c));
    return d;
}
__device__ __forceinline__ u64 pack2(float lo, float hi) {
    u64 d;
    asm("mov.b64 %0, {%1, %2};" : "=l"(d) : "f"(lo), "f"(hi));
    return d;
}
__device__ __forceinline__ float2 unpack2(u64 v) {
    float2 r;
    asm("mov.b64 {%0, %1}, %2;" : "=f"(r.x), "=f"(r.y) : "l"(v));
    return r;
}

// ---------------------------------------------------------------------------
// K0: qk[h][d] = (log2e/SCALE) * sum_j query[h][j] * Wk[h*64+j][d]
// ---------------------------------------------------------------------------
__global__ void k0_qk(const float* __restrict__ Wk, const float* __restrict__ query) {
    int gid = blockIdx.x * 256 + threadIdx.x;   // 16384 = H*D
    int h = gid >> 10;
    int d = gid & 1023;
    const float C = 0.125f * 1.4426950408889634f;   // (1/SCALE) * log2(e)
    float acc = 0.f;
#pragma unroll 8
    for (int j = 0; j < DKK; j++) {
        acc += __ldg(&query[h * DKK + j]) * __ldg(&Wk[(size_t)(h * DKK + j) * DD + d]);
    }
    g_qk[gid] = acc * C;
}

// ---------------------------------------------------------------------------
// FUSED, 512 threads (16 warps), per 16-row tile:
//  Phase A: warp w == head w. Lanes split [2 rows x 16 lanes]; lane sl=l&15
//           holds qk[w][4sl+64i] (32 u64 regs). Per row-pair: 32 FFMA2, then
//           4-shuffle reduce over the 16-lane group; exp2 -> es2[buf][r][w]
//           stored PRE-DUPLICATED as u64 {e,e}.
//  Phase B: thread group grp=t>>8 owns heads 8grp..8grp+7; tt=t&255 owns cols
//           4tt..4tt+3. Column-packed FFMA2: x-pairs free from LDG.128,
//           e-pairs {e,e} free from LDS — zero pack MOVs in the loop.
//  One __syncthreads per tile (double-buffered es2).
// ---------------------------------------------------------------------------
__global__ void __launch_bounds__(512) fused_attn(const float* __restrict__ x) {
    int c = blockIdx.x;
    int b = blockIdx.y;
    int t = threadIdx.x;
    int w = t >> 5, l = t & 31;
    int sl = l & 15, half = l >> 4;
    int grp = t >> 8;          // head group for phase B
    int tt = t & 255;          // column owner for phase B

    __shared__ u64 es2[2][TR][HH];   // duplicated exp pairs, 4 KB

    // qk for head w: lane sl covers d = 4*sl + 64*i, i<16 -> 32 u64
    u64 qkr[32];
    {
        const ulonglong2* qp = (const ulonglong2*)(g_qk + w * DD) + sl;
#pragma unroll
        for (int i = 0; i < 16; i++) {
            ulonglong2 v = qp[16 * i];
            qkr[2 * i] = v.x;
            qkr[2 * i + 1] = v.y;
        }
    }

    // phase B accumulators: head h = 8*grp + hh, col-pairs {4tt+0,1},{4tt+2,3}
    u64 acc[8][2];
#pragma unroll
    for (int hh = 0; hh < 8; hh++) { acc[hh][0] = 0ull; acc[hh][1] = 0ull; }

    float zacc = 0.f;

    int n0 = c * CROWS;
    int nrows = (c == CBLK - 1) ? (NN - (CBLK - 1) * CROWS) : CROWS;
    int ntiles = nrows / TR;

    const float* xb = x + ((size_t)b * NN + n0) * DD;

    for (int tile = 0; tile < ntiles; tile++) {
        const float* xt = xb + (size_t)tile * TR * DD;
        int buf = tile & 1;

        // ---- Phase A ----
#pragma unroll 2
        for (int j = 0; j < 8; j++) {
            int r = 2 * j + half;
            const ulonglong2* xr = (const ulonglong2*)(xt + (size_t)r * DD) + sl;
            u64 a0 = 0ull, a1 = 0ull;
#pragma unroll
            for (int i = 0; i < 16; i++) {
                ulonglong2 xv = __ldg(&xr[16 * i]);
                a0 = ffma2(xv.x, qkr[2 * i], a0);
                a1 = ffma2(xv.y, qkr[2 * i + 1], a1);
            }
            float2 u = unpack2(a0), v = unpack2(a1);
            float s = (u.x + u.y) + (v.x + v.y);
            s += __shfl_xor_sync(0xffffffffu, s, 8);
            s += __shfl_xor_sync(0xffffffffu, s, 4);
            s += __shfl_xor_sync(0xffffffffu, s, 2);
            s += __shfl_xor_sync(0xffffffffu, s, 1);
            if (sl == 0) {
                float e = exp2f(s);
                es2[buf][r][w] = pack2(e, e);
            }
        }
        __syncthreads();

        // ---- Phase B (reads es2[buf]; next Phase A writes the other buffer) ----
#pragma unroll
        for (int r = 0; r < TR; r++) {
            float4 x4 = __ldg((const float4*)(xt + (size_t)r * DD) + tt);
            u64 xlo = pack2(x4.x, x4.y);   // these compile to register pairing of the load
            u64 xhi = pack2(x4.z, x4.w);
            const u64* ep = &es2[buf][r][8 * grp];
#pragma unroll
            for (int hh = 0; hh < 8; hh++) {
                u64 e = ep[hh];            // LDS.64 broadcast, {e,e}
                acc[hh][0] = ffma2(e, xlo, acc[hh][0]);
                acc[hh][1] = ffma2(e, xhi, acc[hh][1]);
            }
        }
        if (t < HH) {
#pragma unroll
            for (int r = 0; r < TR; r++) zacc += unpack2(es2[buf][r][t]).x;
        }
    }

    // ---- epilogue: coalesced float4 partial writes (acc pairs ARE the float4) ----
    size_t base = (size_t)(b * CBLK + c) * HH * DD;
#pragma unroll
    for (int hh = 0; hh < 8; hh++) {
        int h = 8 * grp + hh;
        float2 v0 = unpack2(acc[hh][0]);
        float2 v1 = unpack2(acc[hh][1]);
        *(float4*)&g_ps[base + (size_t)h * DD + 4 * tt] =
            make_float4(v0.x, v0.y, v1.x, v1.y);
    }
    if (t < HH) g_pz[(b * CBLK + c) * HH + t] = zacc;
}

// ---------------------------------------------------------------------------
// K3: combine partials + normalize (z computed inline; uniform-address loads
// broadcast within the warp).  s[b][h][d] = sum_c ps / z[b][h]
// ---------------------------------------------------------------------------
__global__ void k3_combine() {
    size_t gid = (size_t)blockIdx.x * 256 + threadIdx.x;   // B*H*D = 262144
    int b = (int)(gid >> 14);
    int rem = (int)(gid & 16383);          // h*1024 + d
    int h = rem >> 10;
    float z = 0.f;
#pragma unroll
    for (int c = 0; c < CBLK; c++) z += g_pz[(b * CBLK + c) * HH + h];
    float sum = 0.f;
#pragma unroll
    for (int c = 0; c < CBLK; c++) {
        sum += g_ps[(size_t)(b * CBLK + c) * HH * DD + rem];
    }
    g_s[gid] = sum / z;
}

// ---------------------------------------------------------------------------
// K4: pooled[b][o] = Wv[o,:] . s[b][o>>6][:]
// ---------------------------------------------------------------------------
__global__ void __launch_bounds__(256) k4_pooled(const float* __restrict__ Wv) {
    int w = threadIdx.x >> 5, l = threadIdx.x & 31;
    int o = blockIdx.x * 8 + w;
    int b = blockIdx.y;
    int h = o >> 6;
    const float4* wr = (const float4*)(Wv + (size_t)o * DD);
    const float4* sr = (const float4*)(g_s + (size_t)(b * HH + h) * DD);
    float acc = 0.f;
#pragma unroll
    for (int i = 0; i < 8; i++) {
        float4 a = __ldg(&wr[l + 32 * i]);
        float4 s4 = sr[l + 32 * i];
        acc += a.x * s4.x + a.y * s4.y + a.z * s4.z + a.w * s4.w;
    }
    acc += __shfl_xor_sync(0xffffffffu, acc, 16);
    acc += __shfl_xor_sync(0xffffffffu, acc, 8);
    acc += __shfl_xor_sync(0xffffffffu, acc, 4);
    acc += __shfl_xor_sync(0xffffffffu, acc, 2);
    acc += __shfl_xor_sync(0xffffffffu, acc, 1);
    if (l == 0) g_pooled[b * DD + o] = acc;
}

// ---------------------------------------------------------------------------
// K5: out[b][i] = Wout[i,:] . pooled[b,:] + bout[i]
// ---------------------------------------------------------------------------
__global__ void __launch_bounds__(256) k5_out(const float* __restrict__ Wout,
                                              const float* __restrict__ bout,
                                              float* __restrict__ out) {
    int w = threadIdx.x >> 5, l = threadIdx.x & 31;
    int i = blockIdx.x * 8 + w;
    int b = blockIdx.y;
    const float4* wr = (const float4*)(Wout + (size_t)i * DD);
    const float4* pr = (const float4*)(g_pooled + (size_t)b * DD);
    float acc = 0.f;
#pragma unroll
    for (int k = 0; k < 8; k++) {
        float4 a = __ldg(&wr[l + 32 * k]);
        float4 p4 = pr[l + 32 * k];
        acc += a.x * p4.x + a.y * p4.y + a.z * p4.z + a.w * p4.w;
    }
    acc += __shfl_xor_sync(0xffffffffu, acc, 16);
    acc += __shfl_xor_sync(0xffffffffu, acc, 8);
    acc += __shfl_xor_sync(0xffffffffu, acc, 4);
    acc += __shfl_xor_sync(0xffffffffu, acc, 2);
    acc += __shfl_xor_sync(0xffffffffu, acc, 1);
    if (l == 0) out[b * DD + i] = acc + __ldg(&bout[i]);
}

// ---------------------------------------------------------------------------
extern "C" void kernel_launch(void* const* d_in, const int* in_sizes, int n_in,
                              void* d_out, int out_size) {
    const float* x     = (const float*)d_in[0];  // (16,4096,1024)
    const float* Wk    = (const float*)d_in[1];  // (1024,1024)
    const float* Wv    = (const float*)d_in[2];  // (1024,1024)
    const float* query = (const float*)d_in[3];  // (16,1,64)
    const float* Wout  = (const float*)d_in[4];  // (1024,1024)
    const float* bout  = (const float*)d_in[5];  // (1024,)
    float* out = (float*)d_out;                  // (16,1024)

    k0_qk<<<HH * DD / 256, 256>>>(Wk, query);
    fused_attn<<<dim3(CBLK, BB), 512>>>(x);
    k3_combine<<<BB * HH * DD / 256, 256>>>();
    k4_pooled<<<dim3(DD / 8, BB), 256>>>(Wv);
    k5_out<<<dim3(DD / 8, BB), 256>>>(Wout, bout, out);
}

// round 8
// speedup vs baseline: 3.4028x; 3.4028x over previous
#include <cuda_runtime.h>
#include <cstdint>

#define BB 16
#define NN 4096
#define DD 1024
#define HH 16
#define DKK 64
#define CBLK 9            // row-chunks per batch -> 144 blocks ~= 1 wave
#define CROWS 456         // rows per chunk (c<8); last chunk gets 448; both /4
#define TR 4              // tile rows (16 KB/tile, double buffered)

typedef unsigned long long u64;

// ---- scratch (static __device__ — no allocation allowed) ----
__device__ float g_qk[HH * DD];                          // folded (log2e/SCALE) * Q@Wk_head
__device__ float g_ps[(size_t)BB * CBLK * HH * DD];      // partial weighted sums
__device__ float g_pz[BB * CBLK * HH];                   // partial softmax denominators
__device__ float g_s[(size_t)BB * HH * DD];              // normalized weighted avg of x
__device__ float g_pooled[BB * DD];                      // per-head Wv matvec results

// ---- packed f32x2 helpers ----
__device__ __forceinline__ u64 ffma2(u64 a, u64 b, u64 c) {
    u64 d;
    asm("fma.rn.f32x2 %0, %1, %2, %3;" : "=l"(d) : "l"(a), "l"(b), "l"(c));
    return d;
}
__device__ __forceinline__ u64 pack2(float lo, float hi) {
    u64 d;
    asm("mov.b64 %0, {%1, %2};" : "=l"(d) : "f"(lo), "f"(hi));
    return d;
}
__device__ __forceinline__ float2 unpack2(u64 v) {
    float2 r;
    asm("mov.b64 {%0, %1}, %2;" : "=f"(r.x), "=f"(r.y) : "l"(v));
    return r;
}

// ---- cp.async helpers ----
__device__ __forceinline__ void cpasync16(uint32_t saddr, const void* gaddr) {
    asm volatile("cp.async.cg.shared.global [%0], [%1], 16;" :: "r"(saddr), "l"(gaddr));
}
__device__ __forceinline__ void cpasync_commit() {
    asm volatile("cp.async.commit_group;");
}
__device__ __forceinline__ void cpasync_wait0() {
    asm volatile("cp.async.wait_group 0;");
}

// ---------------------------------------------------------------------------
// K0: qk[h][d] = (log2e/SCALE) * sum_j query[h][j] * Wk[h*64+j][d]
// ---------------------------------------------------------------------------
__global__ void k0_qk(const float* __restrict__ Wk, const float* __restrict__ query) {
    int gid = blockIdx.x * 256 + threadIdx.x;   // 16384 = H*D
    int h = gid >> 10;
    int d = gid & 1023;
    const float C = 0.125f * 1.4426950408889634f;   // (1/SCALE) * log2(e)
    float acc = 0.f;
#pragma unroll 8
    for (int j = 0; j < DKK; j++) {
        acc += __ldg(&query[h * DKK + j]) * __ldg(&Wk[(size_t)(h * DKK + j) * DD + d]);
    }
    g_qk[gid] = acc * C;
}

// ---------------------------------------------------------------------------
// FUSED, 256 threads (8 warps), cp.async double-buffered x tiles (TR=4 rows):
//   loop: wait(tile t); sync; prefetch(t+1); PhaseA(t) from smem; sync;
//         PhaseB(t) from smem.
//  Phase A: warp (hg=w&3, p=w>>2) -> heads 4hg..4hg+3, rows p, p+2.
//           qk in regs (qkr[4][16] u64 = 128 regs). 4-shuffle... 5-shuffle
//           reduce per head; es[r][h] written pre-duplicated {e,e}.
//  Phase B: thread t owns cols 4t..4t+3; acc[16][2] u64 (col-pairs).
//           x pairs from LDS.128, e pairs from uniform LDS.64 (broadcast).
// ---------------------------------------------------------------------------
__global__ void __launch_bounds__(256) fused_attn(const float* __restrict__ x) {
    int c = blockIdx.x;
    int b = blockIdx.y;
    int t = threadIdx.x;
    int w = t >> 5, l = t & 31;
    int hg = w & 3, p = w >> 2;

    __shared__ __align__(16) float xs[2][TR * DD];   // 32 KB
    __shared__ __align__(16) u64 es[TR][HH];         // 512 B, {e,e} duplicated

    // qk for my 4 heads: lane l covers d = 4l + 128i (i<8) -> 16 u64 per head
    u64 qkr[4][16];
#pragma unroll
    for (int h = 0; h < 4; h++) {
        const ulonglong2* q = (const ulonglong2*)&g_qk[(4 * hg + h) * DD + 4 * l];
#pragma unroll
        for (int i = 0; i < 8; i++) {
            ulonglong2 v = q[32 * i];
            qkr[h][2 * i] = v.x;
            qkr[h][2 * i + 1] = v.y;
        }
    }

    u64 acc[HH][2];
#pragma unroll
    for (int h = 0; h < HH; h++) { acc[h][0] = 0ull; acc[h][1] = 0ull; }
    float zacc = 0.f;

    int n0 = c * CROWS;
    int nrows = (c == CBLK - 1) ? (NN - (CBLK - 1) * CROWS) : CROWS;
    int ntiles = nrows / TR;

    const char* xg = (const char*)(x + ((size_t)b * NN + n0) * DD);

    // prefetch tile 0
    {
        uint32_t sb = (uint32_t)__cvta_generic_to_shared(&xs[0][0]);
#pragma unroll
        for (int k = 0; k < 4; k++)
            cpasync16(sb + t * 16 + k * 4096, xg + t * 16 + k * 4096);
        cpasync_commit();
    }

    for (int tile = 0; tile < ntiles; tile++) {
        int buf = tile & 1;
        cpasync_wait0();
        __syncthreads();                     // tile `tile` resident in xs[buf]

        // prefetch tile+1 into the other buffer (safe: B(tile-1) done w/ it)
        if (tile + 1 < ntiles) {
            uint32_t sb = (uint32_t)__cvta_generic_to_shared(&xs[buf ^ 1][0]);
            const char* gsrc = xg + (size_t)(tile + 1) * TR * DD * sizeof(float);
#pragma unroll
            for (int k = 0; k < 4; k++)
                cpasync16(sb + t * 16 + k * 4096, gsrc + t * 16 + k * 4096);
            cpasync_commit();
        }

        const float* xt = xs[buf];

        // ---- Phase A: scores (from smem) ----
#pragma unroll
        for (int j = 0; j < 2; j++) {
            int r = p + 2 * j;
            const ulonglong2* xr = (const ulonglong2*)(xt + (size_t)r * DD);
            u64 a0 = 0ull, a1 = 0ull, a2 = 0ull, a3 = 0ull;
#pragma unroll
            for (int i = 0; i < 8; i++) {
                ulonglong2 xv = xr[l + 32 * i];
                a0 = ffma2(xv.x, qkr[0][2 * i], a0);
                a1 = ffma2(xv.x, qkr[1][2 * i], a1);
                a2 = ffma2(xv.x, qkr[2][2 * i], a2);
                a3 = ffma2(xv.x, qkr[3][2 * i], a3);
                a0 = ffma2(xv.y, qkr[0][2 * i + 1], a0);
                a1 = ffma2(xv.y, qkr[1][2 * i + 1], a1);
                a2 = ffma2(xv.y, qkr[2][2 * i + 1], a2);
                a3 = ffma2(xv.y, qkr[3][2 * i + 1], a3);
            }
            float2 f0 = unpack2(a0), f1 = unpack2(a1), f2v = unpack2(a2), f3 = unpack2(a3);
            float s0 = f0.x + f0.y, s1 = f1.x + f1.y, s2 = f2v.x + f2v.y, s3 = f3.x + f3.y;
#pragma unroll
            for (int m = 16; m > 0; m >>= 1) {
                s0 += __shfl_xor_sync(0xffffffffu, s0, m);
                s1 += __shfl_xor_sync(0xffffffffu, s1, m);
                s2 += __shfl_xor_sync(0xffffffffu, s2, m);
                s3 += __shfl_xor_sync(0xffffffffu, s3, m);
            }
            if (l == 0)      { float e = exp2f(s0); es[r][4 * hg + 0] = pack2(e, e); }
            else if (l == 1) { float e = exp2f(s1); es[r][4 * hg + 1] = pack2(e, e); }
            else if (l == 2) { float e = exp2f(s2); es[r][4 * hg + 2] = pack2(e, e); }
            else if (l == 3) { float e = exp2f(s3); es[r][4 * hg + 3] = pack2(e, e); }
        }
        __syncthreads();

        // ---- Phase B: weighted accumulation (x + e from smem) ----
#pragma unroll
        for (int r = 0; r < TR; r++) {
            ulonglong2 xv = ((const ulonglong2*)(xt + (size_t)r * DD))[t]; // {x0,x1},{x2,x3}
            const u64* ep = (const u64*)es[r];
#pragma unroll
            for (int h = 0; h < HH; h++) {
                u64 e = ep[h];              // uniform -> LDS broadcast
                acc[h][0] = ffma2(e, xv.x, acc[h][0]);
                acc[h][1] = ffma2(e, xv.y, acc[h][1]);
            }
        }
        if (t < HH) {
#pragma unroll
            for (int r = 0; r < TR; r++) zacc += unpack2(es[r][t]).x;
        }
        // no trailing sync: next iter's wait+sync precedes any xs/es overwrite
    }

    // ---- epilogue: coalesced float4 partial writes ----
    size_t base = (size_t)(b * CBLK + c) * HH * DD;
#pragma unroll
    for (int h = 0; h < HH; h++) {
        float2 v0 = unpack2(acc[h][0]);
        float2 v1 = unpack2(acc[h][1]);
        *(float4*)&g_ps[base + (size_t)h * DD + 4 * t] =
            make_float4(v0.x, v0.y, v1.x, v1.y);
    }
    if (t < HH) g_pz[(b * CBLK + c) * HH + t] = zacc;
}

// ---------------------------------------------------------------------------
// K3: combine partials + normalize: s[b][h][d] = sum_c ps / z[b][h]
// ---------------------------------------------------------------------------
__global__ void k3_combine() {
    size_t gid = (size_t)blockIdx.x * 256 + threadIdx.x;   // B*H*D = 262144
    int b = (int)(gid >> 14);
    int rem = (int)(gid & 16383);          // h*1024 + d
    int h = rem >> 10;
    float z = 0.f;
#pragma unroll
    for (int c = 0; c < CBLK; c++) z += g_pz[(b * CBLK + c) * HH + h];
    float sum = 0.f;
#pragma unroll
    for (int c = 0; c < CBLK; c++) {
        sum += g_ps[(size_t)(b * CBLK + c) * HH * DD + rem];
    }
    g_s[gid] = sum / z;
}

// ---------------------------------------------------------------------------
// K4: pooled[b][o] = Wv[o,:] . s[b][o>>6][:]  — batched over all 16 b so each
// Wv row is loaded ONCE. warp per o, acc[16].
// ---------------------------------------------------------------------------
__global__ void __launch_bounds__(256) k4_pooled(const float* __restrict__ Wv) {
    int w = threadIdx.x >> 5, l = threadIdx.x & 31;
    int o = blockIdx.x * 8 + w;
    int h = o >> 6;
    float acc[BB];
#pragma unroll
    for (int b = 0; b < BB; b++) acc[b] = 0.f;
    const float4* wr = (const float4*)(Wv + (size_t)o * DD);
#pragma unroll
    for (int i = 0; i < 8; i++) {
        float4 a = __ldg(&wr[l + 32 * i]);
#pragma unroll
        for (int b = 0; b < BB; b++) {
            float4 s4 = *(const float4*)&g_s[(size_t)(b * HH + h) * DD + 4 * (l + 32 * i)];
            acc[b] += a.x * s4.x + a.y * s4.y + a.z * s4.z + a.w * s4.w;
        }
    }
#pragma unroll
    for (int b = 0; b < BB; b++) {
        float v = acc[b];
        v += __shfl_xor_sync(0xffffffffu, v, 16);
        v += __shfl_xor_sync(0xffffffffu, v, 8);
        v += __shfl_xor_sync(0xffffffffu, v, 4);
        v += __shfl_xor_sync(0xffffffffu, v, 2);
        v += __shfl_xor_sync(0xffffffffu, v, 1);
        if (l == 0) g_pooled[b * DD + o] = v;
    }
}

// ---------------------------------------------------------------------------
// K5: out[b][i] = Wout[i,:] . pooled[b,:] + bout[i] — batched over b likewise.
// ---------------------------------------------------------------------------
__global__ void __launch_bounds__(256) k5_out(const float* __restrict__ Wout,
                                              const float* __restrict__ bout,
                                              float* __restrict__ out) {
    int w = threadIdx.x >> 5, l = threadIdx.x & 31;
    int i = blockIdx.x * 8 + w;
    float acc[BB];
#pragma unroll
    for (int b = 0; b < BB; b++) acc[b] = 0.f;
    const float4* wr = (const float4*)(Wout + (size_t)i * DD);
#pragma unroll
    for (int k = 0; k < 8; k++) {
        float4 a = __ldg(&wr[l + 32 * k]);
#pragma unroll
        for (int b = 0; b < BB; b++) {
            float4 p4 = *(const float4*)&g_pooled[(size_t)b * DD + 4 * (l + 32 * k)];
            acc[b] += a.x * p4.x + a.y * p4.y + a.z * p4.z + a.w * p4.w;
        }
    }
    float bo = __ldg(&bout[i]);
#pragma unroll
    for (int b = 0; b < BB; b++) {
        float v = acc[b];
        v += __shfl_xor_sync(0xffffffffu, v, 16);
        v += __shfl_xor_sync(0xffffffffu, v, 8);
        v += __shfl_xor_sync(0xffffffffu, v, 4);
        v += __shfl_xor_sync(0xffffffffu, v, 2);
        v += __shfl_xor_sync(0xffffffffu, v, 1);
        if (l == 0) out[b * DD + i] = v + bo;
    }
}

// ---------------------------------------------------------------------------
extern "C" void kernel_launch(void* const* d_in, const int* in_sizes, int n_in,
                              void* d_out, int out_size) {
    const float* x     = (const float*)d_in[0];  // (16,4096,1024)
    const float* Wk    = (const float*)d_in[1];  // (1024,1024)
    const float* Wv    = (const float*)d_in[2];  // (1024,1024)
    const float* query = (const float*)d_in[3];  // (16,1,64)
    const float* Wout  = (const float*)d_in[4];  // (1024,1024)
    const float* bout  = (const float*)d_in[5];  // (1024,)
    float* out = (float*)d_out;                  // (16,1024)

    k0_qk<<<HH * DD / 256, 256>>>(Wk, query);
    fused_attn<<<dim3(CBLK, BB), 256>>>(x);
    k3_combine<<<BB * HH * DD / 256, 256>>>();
    k4_pooled<<<DD / 8, 256>>>(Wv);
    k5_out<<<DD / 8, 256>>>(Wout, bout, out);
}

// round 10
// speedup vs baseline: 3.8849x; 1.1417x over previous
#include <cuda_runtime.h>
#include <cstdint>

#define BB 16
#define NN 4096
#define DD 1024
#define HH 16
#define DKK 64
#define CBLK 9            // row-chunks per batch -> 144 blocks ~= 1 wave
#define CROWS 456         // rows per chunk (c<8); last gets 448; both /8
#define TR 8              // tile rows (32 KB/tile)
#define XBUF 4            // quad-buffered tiles (skewed pipeline safety)

typedef unsigned long long u64;

// ---- scratch (static __device__ — no allocation allowed) ----
__device__ float g_qk[HH * DD];
__device__ float g_ps[(size_t)BB * CBLK * HH * DD];
__device__ float g_pz[BB * CBLK * HH];
__device__ float g_s[(size_t)BB * HH * DD];
__device__ float g_pooled[BB * DD];

// ---- packed f32x2 helpers ----
__device__ __forceinline__ u64 ffma2(u64 a, u64 b, u64 c) {
    u64 d;
    asm("fma.rn.f32x2 %0, %1, %2, %3;" : "=l"(d) : "l"(a), "l"(b), "l"(c));
    return d;
}
__device__ __forceinline__ u64 pack2(float lo, float hi) {
    u64 d;
    asm("mov.b64 %0, {%1, %2};" : "=l"(d) : "f"(lo), "f"(hi));
    return d;
}
__device__ __forceinline__ float2 unpack2(u64 v) {
    float2 r;
    asm("mov.b64 {%0, %1}, %2;" : "=f"(r.x), "=f"(r.y) : "l"(v));
    return r;
}

// ---- cp.async helpers ----
__device__ __forceinline__ void cpasync16(uint32_t saddr, const void* gaddr) {
    asm volatile("cp.async.cg.shared.global [%0], [%1], 16;" :: "r"(saddr), "l"(gaddr));
}
__device__ __forceinline__ void cpasync_commit() {
    asm volatile("cp.async.commit_group;");
}
__device__ __forceinline__ void cpasync_wait0() {
    asm volatile("cp.async.wait_group 0;");
}
__device__ __forceinline__ void cpasync_wait1() {
    asm volatile("cp.async.wait_group 1;");
}

// ---------------------------------------------------------------------------
// K0: qk[h][d] = (log2e/SCALE) * sum_j query[h][j] * Wk[h*64+j][d]
// ---------------------------------------------------------------------------
__global__ void k0_qk(const float* __restrict__ Wk, const float* __restrict__ query) {
    int gid = blockIdx.x * 256 + threadIdx.x;   // 16384 = H*D
    int h = gid >> 10;
    int d = gid & 1023;
    const float C = 0.125f * 1.4426950408889634f;
    float acc = 0.f;
#pragma unroll 8
    for (int j = 0; j < DKK; j++) {
        acc += __ldg(&query[h * DKK + j]) * __ldg(&Wk[(size_t)(h * DKK + j) * DD + d]);
    }
    g_qk[gid] = acc * C;
}

// ---------------------------------------------------------------------------
// FUSED v3 — skewed pipeline, 256 threads, quad-buffered 8-row tiles.
// iter t: wait(xs[t]); sync; commit prefetch(t+2);
//         PhaseA(t)  -> es[t&1]   (warp (hg,p): heads 4hg..4hg+3, rows p+2j)
//         PhaseB(t-1) <- es[(t-1)&1], xs[(t-1)%4]  (thread owns cols 4t..4t+3)
// ONE __syncthreads per 8 rows; A's shuffle latency overlaps B's FFMA2 stream.
// ---------------------------------------------------------------------------
__global__ void __launch_bounds__(256) fused_attn(const float* __restrict__ x) {
    extern __shared__ __align__(16) float xs[];     // XBUF * TR * DD floats (128 KB)
    __shared__ __align__(16) u64 es[2][TR][HH];     // {e,e}-duplicated, parity buffered

    int c = blockIdx.x;
    int b = blockIdx.y;
    int t = threadIdx.x;
    int w = t >> 5, l = t & 31;
    int hg = w & 3, p = w >> 2;

    // qk for my 4 heads: lane l covers d = 4l + 128i (i<8) -> 16 u64 per head
    u64 qkr[4][16];
#pragma unroll
    for (int h = 0; h < 4; h++) {
        const ulonglong2* q = (const ulonglong2*)&g_qk[(4 * hg + h) * DD + 4 * l];
#pragma unroll
        for (int i = 0; i < 8; i++) {
            ulonglong2 v = q[32 * i];
            qkr[h][2 * i] = v.x;
            qkr[h][2 * i + 1] = v.y;
        }
    }

    u64 acc[HH][2];
#pragma unroll
    for (int h = 0; h < HH; h++) { acc[h][0] = 0ull; acc[h][1] = 0ull; }
    float zacc = 0.f;

    int n0 = c * CROWS;
    int nrows = (c == CBLK - 1) ? (NN - (CBLK - 1) * CROWS) : CROWS;
    int ntiles = nrows / TR;                       // 57 or 56

    const char* xg = (const char*)(x + ((size_t)b * NN + n0) * DD);
    const size_t TILEB = (size_t)TR * DD * 4;      // 32768 bytes

    // prologue: prefetch tiles 0 and 1
#pragma unroll
    for (int pf = 0; pf < 2; pf++) {
        uint32_t sb = (uint32_t)__cvta_generic_to_shared(xs + pf * TR * DD);
        const char* g = xg + (size_t)pf * TILEB;
#pragma unroll
        for (int k2 = 0; k2 < 8; k2++)
            cpasync16(sb + t * 16 + k2 * 4096, g + t * 16 + k2 * 4096);
        cpasync_commit();
    }

    for (int tile = 0; tile <= ntiles; tile++) {
        if (tile < ntiles) {
            if (tile + 1 < ntiles) cpasync_wait1();  // xs[tile] done, xs[tile+1] may fly
            else                   cpasync_wait0();
        }
        __syncthreads();   // xs[tile%4] resident; all warps done with iter tile-1

        // prefetch tile+2 into buf (tile+2)%4 — disjoint from A(tile) and B(tile-1)
        if (tile + 2 < ntiles) {
            uint32_t sb = (uint32_t)__cvta_generic_to_shared(
                xs + ((tile + 2) & 3) * TR * DD);
            const char* g = xg + (size_t)(tile + 2) * TILEB;
#pragma unroll
            for (int k2 = 0; k2 < 8; k2++)
                cpasync16(sb + t * 16 + k2 * 4096, g + t * 16 + k2 * 4096);
            cpasync_commit();
        }

        // ---- Phase A(tile): scores -> es[tile&1] ----
        if (tile < ntiles) {
            const float* xt = xs + (tile & 3) * TR * DD;
            u64 (*eo)[HH] = es[tile & 1];
#pragma unroll 2
            for (int j = 0; j < 4; j++) {
                int r = p + 2 * j;
                const ulonglong2* xr = (const ulonglong2*)(xt + (size_t)r * DD);
                u64 a0 = 0ull, a1 = 0ull, a2 = 0ull, a3 = 0ull;
#pragma unroll
                for (int i = 0; i < 8; i++) {
                    ulonglong2 xv = xr[l + 32 * i];
                    a0 = ffma2(xv.x, qkr[0][2 * i], a0);
                    a1 = ffma2(xv.x, qkr[1][2 * i], a1);
                    a2 = ffma2(xv.x, qkr[2][2 * i], a2);
                    a3 = ffma2(xv.x, qkr[3][2 * i], a3);
                    a0 = ffma2(xv.y, qkr[0][2 * i + 1], a0);
                    a1 = ffma2(xv.y, qkr[1][2 * i + 1], a1);
                    a2 = ffma2(xv.y, qkr[2][2 * i + 1], a2);
                    a3 = ffma2(xv.y, qkr[3][2 * i + 1], a3);
                }
                float2 f0 = unpack2(a0), f1 = unpack2(a1);
                float2 f2v = unpack2(a2), f3 = unpack2(a3);
                float s0 = f0.x + f0.y, s1 = f1.x + f1.y;
                float s2 = f2v.x + f2v.y, s3 = f3.x + f3.y;
#pragma unroll
                for (int m = 16; m > 0; m >>= 1) {
                    s0 += __shfl_xor_sync(0xffffffffu, s0, m);
                    s1 += __shfl_xor_sync(0xffffffffu, s1, m);
                    s2 += __shfl_xor_sync(0xffffffffu, s2, m);
                    s3 += __shfl_xor_sync(0xffffffffu, s3, m);
                }
                if (l == 0)      { float e = exp2f(s0); eo[r][4 * hg + 0] = pack2(e, e); }
                else if (l == 1) { float e = exp2f(s1); eo[r][4 * hg + 1] = pack2(e, e); }
                else if (l == 2) { float e = exp2f(s2); eo[r][4 * hg + 2] = pack2(e, e); }
                else if (l == 3) { float e = exp2f(s3); eo[r][4 * hg + 3] = pack2(e, e); }
            }
        }

        // ---- Phase B(tile-1): weighted accumulation ----
        if (tile >= 1) {
            const float* xt = xs + ((tile - 1) & 3) * TR * DD;
            const u64 (*eb)[HH] = es[(tile - 1) & 1];
#pragma unroll
            for (int r = 0; r < TR; r++) {
                ulonglong2 xv = ((const ulonglong2*)(xt + (size_t)r * DD))[t];
                const u64* ep = eb[r];
#pragma unroll
                for (int h = 0; h < HH; h++) {
                    u64 e = ep[h];           // uniform -> LDS broadcast
                    acc[h][0] = ffma2(e, xv.x, acc[h][0]);
                    acc[h][1] = ffma2(e, xv.y, acc[h][1]);
                }
            }
            if (t < HH) {
#pragma unroll
                for (int r = 0; r < TR; r++) zacc += unpack2(eb[r][t]).x;
            }
        }
    }

    // ---- epilogue: coalesced float4 partial writes ----
    size_t base = (size_t)(b * CBLK + c) * HH * DD;
#pragma unroll
    for (int h = 0; h < HH; h++) {
        float2 v0 = unpack2(acc[h][0]);
        float2 v1 = unpack2(acc[h][1]);
        *(float4*)&g_ps[base + (size_t)h * DD + 4 * t] =
            make_float4(v0.x, v0.y, v1.x, v1.y);
    }
    if (t < HH) g_pz[(b * CBLK + c) * HH + t] = zacc;
}

// ---------------------------------------------------------------------------
// K3: combine partials + normalize: s[b][h][d] = sum_c ps / z[b][h]
// ---------------------------------------------------------------------------
__global__ void k3_combine() {
    size_t gid = (size_t)blockIdx.x * 256 + threadIdx.x;   // B*H*D = 262144
    int b = (int)(gid >> 14);
    int rem = (int)(gid & 16383);
    int h = rem >> 10;
    float z = 0.f;
#pragma unroll
    for (int c = 0; c < CBLK; c++) z += g_pz[(b * CBLK + c) * HH + h];
    float sum = 0.f;
#pragma unroll
    for (int c = 0; c < CBLK; c++) {
        sum += g_ps[(size_t)(b * CBLK + c) * HH * DD + rem];
    }
    g_s[gid] = sum / z;
}

// ---------------------------------------------------------------------------
// K4: pooled[b][o] = Wv[o,:] . s[b][o>>6][:]  (2048-block version — measured
// better than batched-b at this size)
// ---------------------------------------------------------------------------
__global__ void __launch_bounds__(256) k4_pooled(const float* __restrict__ Wv) {
    int w = threadIdx.x >> 5, l = threadIdx.x & 31;
    int o = blockIdx.x * 8 + w;
    int b = blockIdx.y;
    int h = o >> 6;
    const float4* wr = (const float4*)(Wv + (size_t)o * DD);
    const float4* sr = (const float4*)(g_s + (size_t)(b * HH + h) * DD);
    float acc = 0.f;
#pragma unroll
    for (int i = 0; i < 8; i++) {
        float4 a = __ldg(&wr[l + 32 * i]);
        float4 s4 = sr[l + 32 * i];
        acc += a.x * s4.x + a.y * s4.y + a.z * s4.z + a.w * s4.w;
    }
    acc += __shfl_xor_sync(0xffffffffu, acc, 16);
    acc += __shfl_xor_sync(0xffffffffu, acc, 8);
    acc += __shfl_xor_sync(0xffffffffu, acc, 4);
    acc += __shfl_xor_sync(0xffffffffu, acc, 2);
    acc += __shfl_xor_sync(0xffffffffu, acc, 1);
    if (l == 0) g_pooled[b * DD + o] = acc;
}

// ---------------------------------------------------------------------------
// K5: out[b][i] = Wout[i,:] . pooled[b,:] + bout[i]
// ---------------------------------------------------------------------------
__global__ void __launch_bounds__(256) k5_out(const float* __restrict__ Wout,
                                              const float* __restrict__ bout,
                                              float* __restrict__ out) {
    int w = threadIdx.x >> 5, l = threadIdx.x & 31;
    int i = blockIdx.x * 8 + w;
    int b = blockIdx.y;
    const float4* wr = (const float4*)(Wout + (size_t)i * DD);
    const float4* pr = (const float4*)(g_pooled + (size_t)b * DD);
    float acc = 0.f;
#pragma unroll
    for (int k = 0; k < 8; k++) {
        float4 a = __ldg(&wr[l + 32 * k]);
        float4 p4 = pr[l + 32 * k];
        acc += a.x * p4.x + a.y * p4.y + a.z * p4.z + a.w * p4.w;
    }
    acc += __shfl_xor_sync(0xffffffffu, acc, 16);
    acc += __shfl_xor_sync(0xffffffffu, acc, 8);
    acc += __shfl_xor_sync(0xffffffffu, acc, 4);
    acc += __shfl_xor_sync(0xffffffffu, acc, 2);
    acc += __shfl_xor_sync(0xffffffffu, acc, 1);
    if (l == 0) out[b * DD + i] = acc + __ldg(&bout[i]);
}

// ---------------------------------------------------------------------------
extern "C" void kernel_launch(void* const* d_in, const int* in_sizes, int n_in,
                              void* d_out, int out_size) {
    const float* x     = (const float*)d_in[0];  // (16,4096,1024)
    const float* Wk    = (const float*)d_in[1];  // (1024,1024)
    const float* Wv    = (const float*)d_in[2];  // (1024,1024)
    const float* query = (const float*)d_in[3];  // (16,1,64)
    const float* Wout  = (const float*)d_in[4];  // (1024,1024)
    const float* bout  = (const float*)d_in[5];  // (1024,)
    float* out = (float*)d_out;                  // (16,1024)

    const int XS_BYTES = XBUF * TR * DD * 4;     // 131072
    cudaFuncSetAttribute(fused_attn,
                         cudaFuncAttributeMaxDynamicSharedMemorySize, XS_BYTES);

    k0_qk<<<HH * DD / 256, 256>>>(Wk, query);
    fused_attn<<<dim3(CBLK, BB), 256, XS_BYTES>>>(x);
    k3_combine<<<BB * HH * DD / 256, 256>>>();
    k4_pooled<<<dim3(DD / 8, BB), 256>>>(Wv);
    k5_out<<<dim3(DD / 8, BB), 256>>>(Wout, bout, out);
}

// round 13
// speedup vs baseline: 4.2076x; 1.0831x over previous
#include <cuda_runtime.h>
#include <cstdint>

#define BB 16
#define NN 4096
#define DD 1024
#define HH 16
#define DKK 64
#define CBLK 9            // row-chunks per batch -> 144 blocks ~= 1 wave
#define CROWS 456         // rows per chunk (c<8); last gets 448; both /8
#define TR 8              // tile rows (32 KB/tile)
#define XBUF 4            // quad-buffered tiles

typedef unsigned long long u64;

// ---- scratch (static __device__ — no allocation allowed) ----
__device__ float g_qk[HH * DD];
__device__ float g_ps[(size_t)BB * CBLK * HH * DD];
__device__ float g_pz[BB * CBLK * HH];
__device__ float g_s[(size_t)BB * HH * DD];
__device__ float g_pooled[BB * DD];

// ---- packed f32x2 helpers ----
__device__ __forceinline__ u64 ffma2(u64 a, u64 b, u64 c) {
    u64 d;
    asm("fma.rn.f32x2 %0, %1, %2, %3;" : "=l"(d) : "l"(a), "l"(b), "l"(c));
    return d;
}
__device__ __forceinline__ u64 pack2(float lo, float hi) {
    u64 d;
    asm("mov.b64 %0, {%1, %2};" : "=l"(d) : "f"(lo), "f"(hi));
    return d;
}
__device__ __forceinline__ float2 unpack2(u64 v) {
    float2 r;
    asm("mov.b64 {%0, %1}, %2;" : "=f"(r.x), "=f"(r.y) : "l"(v));
    return r;
}

// ---- cp.async helpers ----
__device__ __forceinline__ void cpasync16(uint32_t saddr, const void* gaddr) {
    asm volatile("cp.async.cg.shared.global [%0], [%1], 16;" :: "r"(saddr), "l"(gaddr));
}
__device__ __forceinline__ void cpasync_commit() {
    asm volatile("cp.async.commit_group;");
}
__device__ __forceinline__ void cpasync_wait0() {
    asm volatile("cp.async.wait_group 0;");
}
__device__ __forceinline__ void cpasync_wait1() {
    asm volatile("cp.async.wait_group 1;");
}

// ---------------------------------------------------------------------------
// K0: qk[h][d] = (log2e/SCALE) * sum_j query[h][j] * Wk[h*64+j][d]
// ---------------------------------------------------------------------------
__global__ void k0_qk(const float* __restrict__ Wk, const float* __restrict__ query) {
    int gid = blockIdx.x * 256 + threadIdx.x;   // 16384 = H*D
    int h = gid >> 10;
    int d = gid & 1023;
    const float C = 0.125f * 1.4426950408889634f;
    float acc = 0.f;
#pragma unroll 8
    for (int j = 0; j < DKK; j++) {
        acc += __ldg(&query[h * DKK + j]) * __ldg(&Wk[(size_t)(h * DKK + j) * DD + d]);
    }
    g_qk[gid] = acc * C;
}

// ---------------------------------------------------------------------------
// A-chunk: scores for rows p+2j (this warp's 4 heads) -> eo  (64 FFMA2)
// ---------------------------------------------------------------------------
__device__ __forceinline__ void phaseA_j(const float* xt, u64 (*eo)[HH],
                                         const u64 qkr[4][16],
                                         int j, int l, int hg, int p) {
    int r = p + 2 * j;
    const ulonglong2* xr = (const ulonglong2*)(xt + (size_t)r * DD);
    u64 a0 = 0ull, a1 = 0ull, a2 = 0ull, a3 = 0ull;
#pragma unroll
    for (int i = 0; i < 8; i++) {
        ulonglong2 xv = xr[l + 32 * i];
        a0 = ffma2(xv.x, qkr[0][2 * i], a0);
        a1 = ffma2(xv.x, qkr[1][2 * i], a1);
        a2 = ffma2(xv.x, qkr[2][2 * i], a2);
        a3 = ffma2(xv.x, qkr[3][2 * i], a3);
        a0 = ffma2(xv.y, qkr[0][2 * i + 1], a0);
        a1 = ffma2(xv.y, qkr[1][2 * i + 1], a1);
        a2 = ffma2(xv.y, qkr[2][2 * i + 1], a2);
        a3 = ffma2(xv.y, qkr[3][2 * i + 1], a3);
    }
    float2 f0 = unpack2(a0), f1 = unpack2(a1), f2v = unpack2(a2), f3 = unpack2(a3);
    float s0 = f0.x + f0.y, s1 = f1.x + f1.y, s2 = f2v.x + f2v.y, s3 = f3.x + f3.y;
#pragma unroll
    for (int m = 16; m > 0; m >>= 1) {
        s0 += __shfl_xor_sync(0xffffffffu, s0, m);
        s1 += __shfl_xor_sync(0xffffffffu, s1, m);
        s2 += __shfl_xor_sync(0xffffffffu, s2, m);
        s3 += __shfl_xor_sync(0xffffffffu, s3, m);
    }
    if (l == 0)      { float e = exp2f(s0); eo[r][4 * hg + 0] = pack2(e, e); }
    else if (l == 1) { float e = exp2f(s1); eo[r][4 * hg + 1] = pack2(e, e); }
    else if (l == 2) { float e = exp2f(s2); eo[r][4 * hg + 2] = pack2(e, e); }
    else if (l == 3) { float e = exp2f(s3); eo[r][4 * hg + 3] = pack2(e, e); }
}

// ---------------------------------------------------------------------------
// B-chunk: weighted accumulation of one row (32 FFMA2, e via LDS.128 pairs)
// ---------------------------------------------------------------------------
__device__ __forceinline__ void phaseB_row(const float* xt, const u64 (*eb)[HH],
                                           u64 acc[HH][2], int r, int t) {
    ulonglong2 xv = ((const ulonglong2*)(xt + (size_t)r * DD))[t];
    const ulonglong2* ep = (const ulonglong2*)eb[r];
#pragma unroll
    for (int hh = 0; hh < 8; hh++) {
        ulonglong2 e2 = ep[hh];              // uniform -> LDS.128 broadcast
        acc[2 * hh][0]     = ffma2(e2.x, xv.x, acc[2 * hh][0]);
        acc[2 * hh][1]     = ffma2(e2.x, xv.y, acc[2 * hh][1]);
        acc[2 * hh + 1][0] = ffma2(e2.y, xv.x, acc[2 * hh + 1][0]);
        acc[2 * hh + 1][1] = ffma2(e2.y, xv.y, acc[2 * hh + 1][1]);
    }
}

// ---------------------------------------------------------------------------
// FUSED v4 — skewed pipeline with INSTRUCTION-LEVEL A/B interleave.
// main loop iter t (1..ntiles-1): wait; sync; prefetch(t+2);
//   for j in 0..3: { A(t, rows p+2j) ; B(t-1, rows 2j, 2j+1) }   <- one BB
// A(tile0) and B(last tile) peeled. One __syncthreads per tile.
// ---------------------------------------------------------------------------
__global__ void __launch_bounds__(256) fused_attn(const float* __restrict__ x) {
    extern __shared__ __align__(16) float xs[];     // XBUF * TR * DD floats (128 KB)
    __shared__ __align__(16) u64 es[2][TR][HH];     // {e,e}-duplicated, parity buffered

    int c = blockIdx.x;
    int b = blockIdx.y;
    int t = threadIdx.x;
    int w = t >> 5, l = t & 31;
    int hg = w & 3, p = w >> 2;

    u64 qkr[4][16];
#pragma unroll
    for (int h = 0; h < 4; h++) {
        const ulonglong2* q = (const ulonglong2*)&g_qk[(4 * hg + h) * DD + 4 * l];
#pragma unroll
        for (int i = 0; i < 8; i++) {
            ulonglong2 v = q[32 * i];
            qkr[h][2 * i] = v.x;
            qkr[h][2 * i + 1] = v.y;
        }
    }

    u64 acc[HH][2];
#pragma unroll
    for (int h = 0; h < HH; h++) { acc[h][0] = 0ull; acc[h][1] = 0ull; }
    float zacc = 0.f;

    int n0 = c * CROWS;
    int nrows = (c == CBLK - 1) ? (NN - (CBLK - 1) * CROWS) : CROWS;
    int ntiles = nrows / TR;                       // 57 or 56

    const char* xg = (const char*)(x + ((size_t)b * NN + n0) * DD);
    const size_t TILEB = (size_t)TR * DD * 4;      // 32768 bytes

    // prologue: prefetch tiles 0 and 1
#pragma unroll
    for (int pf = 0; pf < 2; pf++) {
        uint32_t sb = (uint32_t)__cvta_generic_to_shared(xs + pf * TR * DD);
        const char* g = xg + (size_t)pf * TILEB;
#pragma unroll
        for (int k2 = 0; k2 < 8; k2++)
            cpasync16(sb + t * 16 + k2 * 4096, g + t * 16 + k2 * 4096);
        cpasync_commit();
    }

    // ---- peeled tile 0: A only ----
    {
        if (1 < ntiles) cpasync_wait1(); else cpasync_wait0();
        __syncthreads();
        if (2 < ntiles) {
            uint32_t sb = (uint32_t)__cvta_generic_to_shared(xs + 2 * TR * DD);
            const char* g = xg + 2 * TILEB;
#pragma unroll
            for (int k2 = 0; k2 < 8; k2++)
                cpasync16(sb + t * 16 + k2 * 4096, g + t * 16 + k2 * 4096);
            cpasync_commit();
        }
        const float* xt = xs;                      // buf 0
#pragma unroll
        for (int j = 0; j < 4; j++) phaseA_j(xt, es[0], qkr, j, l, hg, p);
    }

    // ---- main loop: interleaved A(tile) + B(tile-1) ----
    for (int tile = 1; tile < ntiles; tile++) {
        if (tile + 1 < ntiles) cpasync_wait1();
        else                   cpasync_wait0();
        __syncthreads();   // xs[tile&3] resident; es[(tile-1)&1] complete

        if (tile + 2 < ntiles) {
            uint32_t sb = (uint32_t)__cvta_generic_to_shared(
                xs + ((tile + 2) & 3) * TR * DD);
            const char* g = xg + (size_t)(tile + 2) * TILEB;
#pragma unroll
            for (int k2 = 0; k2 < 8; k2++)
                cpasync16(sb + t * 16 + k2 * 4096, g + t * 16 + k2 * 4096);
            cpasync_commit();
        }

        const float* xta = xs + (tile & 3) * TR * DD;
        const float* xtb = xs + ((tile - 1) & 3) * TR * DD;
        u64 (*eo)[HH] = es[tile & 1];
        const u64 (*eb)[HH] = (const u64 (*)[HH])es[(tile - 1) & 1];

#pragma unroll
        for (int j = 0; j < 4; j++) {
            phaseA_j(xta, eo, qkr, j, l, hg, p);     // independent of B below
            phaseB_row(xtb, eb, acc, 2 * j, t);
            phaseB_row(xtb, eb, acc, 2 * j + 1, t);
        }
        if (t < HH) {
#pragma unroll
            for (int r = 0; r < TR; r++) zacc += unpack2(eb[r][t]).x;
        }
    }

    // ---- peeled final B(ntiles-1) ----
    __syncthreads();
    {
        const float* xtb = xs + ((ntiles - 1) & 3) * TR * DD;
        const u64 (*eb)[HH] = (const u64 (*)[HH])es[(ntiles - 1) & 1];
#pragma unroll
        for (int r = 0; r < TR; r++) phaseB_row(xtb, eb, acc, r, t);
        if (t < HH) {
#pragma unroll
            for (int r = 0; r < TR; r++) zacc += unpack2(eb[r][t]).x;
        }
    }

    // ---- epilogue: coalesced float4 partial writes ----
    size_t base = (size_t)(b * CBLK + c) * HH * DD;
#pragma unroll
    for (int h = 0; h < HH; h++) {
        float2 v0 = unpack2(acc[h][0]);
        float2 v1 = unpack2(acc[h][1]);
        *(float4*)&g_ps[base + (size_t)h * DD + 4 * t] =
            make_float4(v0.x, v0.y, v1.x, v1.y);
    }
    if (t < HH) g_pz[(b * CBLK + c) * HH + t] = zacc;
}

// ---------------------------------------------------------------------------
// K3: combine partials + normalize: s[b][h][d] = sum_c ps / z[b][h]
// ---------------------------------------------------------------------------
__global__ void k3_combine() {
    size_t gid = (size_t)blockIdx.x * 256 + threadIdx.x;   // B*H*D = 262144
    int b = (int)(gid >> 14);
    int rem = (int)(gid & 16383);
    int h = rem >> 10;
    float z = 0.f;
#pragma unroll
    for (int c = 0; c < CBLK; c++) z += g_pz[(b * CBLK + c) * HH + h];
    float sum = 0.f;
#pragma unroll
    for (int c = 0; c < CBLK; c++) {
        sum += g_ps[(size_t)(b * CBLK + c) * HH * DD + rem];
    }
    g_s[gid] = sum / z;
}

// ---------------------------------------------------------------------------
// K4: pooled[b][o] = Wv[o,:] . s[b][o>>6][:]
// ---------------------------------------------------------------------------
__global__ void __launch_bounds__(256) k4_pooled(const float* __restrict__ Wv) {
    int w = threadIdx.x >> 5, l = threadIdx.x & 31;
    int o = blockIdx.x * 8 + w;
    int b = blockIdx.y;
    int h = o >> 6;
    const float4* wr = (const float4*)(Wv + (size_t)o * DD);
    const float4* sr = (const float4*)(g_s + (size_t)(b * HH + h) * DD);
    float acc = 0.f;
#pragma unroll
    for (int i = 0; i < 8; i++) {
        float4 a = __ldg(&wr[l + 32 * i]);
        float4 s4 = sr[l + 32 * i];
        acc += a.x * s4.x + a.y * s4.y + a.z * s4.z + a.w * s4.w;
    }
    acc += __shfl_xor_sync(0xffffffffu, acc, 16);
    acc += __shfl_xor_sync(0xffffffffu, acc, 8);
    acc += __shfl_xor_sync(0xffffffffu, acc, 4);
    acc += __shfl_xor_sync(0xffffffffu, acc, 2);
    acc += __shfl_xor_sync(0xffffffffu, acc, 1);
    if (l == 0) g_pooled[b * DD + o] = acc;
}

// ---------------------------------------------------------------------------
// K5: out[b][i] = Wout[i,:] . pooled[b,:] + bout[i]
// ---------------------------------------------------------------------------
__global__ void __launch_bounds__(256) k5_out(const float* __restrict__ Wout,
                                              const float* __restrict__ bout,
                                              float* __restrict__ out) {
    int w = threadIdx.x >> 5, l = threadIdx.x & 31;
    int i = blockIdx.x * 8 + w;
    int b = blockIdx.y;
    const float4* wr = (const float4*)(Wout + (size_t)i * DD);
    const float4* pr = (const float4*)(g_pooled + (size_t)b * DD);
    float acc = 0.f;
#pragma unroll
    for (int k = 0; k < 8; k++) {
        float4 a = __ldg(&wr[l + 32 * k]);
        float4 p4 = pr[l + 32 * k];
        acc += a.x * p4.x + a.y * p4.y + a.z * p4.z + a.w * p4.w;
    }
    acc += __shfl_xor_sync(0xffffffffu, acc, 16);
    acc += __shfl_xor_sync(0xffffffffu, acc, 8);
    acc += __shfl_xor_sync(0xffffffffu, acc, 4);
    acc += __shfl_xor_sync(0xffffffffu, acc, 2);
    acc += __shfl_xor_sync(0xffffffffu, acc, 1);
    if (l == 0) out[b * DD + i] = acc + __ldg(&bout[i]);
}

// ---------------------------------------------------------------------------
extern "C" void kernel_launch(void* const* d_in, const int* in_sizes, int n_in,
                              void* d_out, int out_size) {
    const float* x     = (const float*)d_in[0];  // (16,4096,1024)
    const float* Wk    = (const float*)d_in[1];  // (1024,1024)
    const float* Wv    = (const float*)d_in[2];  // (1024,1024)
    const float* query = (const float*)d_in[3];  // (16,1,64)
    const float* Wout  = (const float*)d_in[4];  // (1024,1024)
    const float* bout  = (const float*)d_in[5];  // (1024,)
    float* out = (float*)d_out;                  // (16,1024)

    const int XS_BYTES = XBUF * TR * DD * 4;     // 131072
    cudaFuncSetAttribute(fused_attn,
                         cudaFuncAttributeMaxDynamicSharedMemorySize, XS_BYTES);

    k0_qk<<<HH * DD / 256, 256>>>(Wk, query);
    fused_attn<<<dim3(CBLK, BB), 256, XS_BYTES>>>(x);
    k3_combine<<<BB * HH * DD / 256, 256>>>();
    k4_pooled<<<dim3(DD / 8, BB), 256>>>(Wv);
    k5_out<<<dim3(DD / 8, BB), 256>>>(Wout, bout, out);
}

// round 14
// speedup vs baseline: 5.1695x; 1.2286x over previous
#include <cuda_runtime.h>
#include <cstdint>

#define BB 16
#define NN 4096
#define DD 1024
#define HH 16
#define DKK 64
#define CBLK 9            // row-chunks per batch -> 144 blocks ~= 1 wave
#define CROWS 456         // rows per chunk (c<8); last gets 448; both /8
#define TR 8              // tile rows (32 KB/tile)
#define XBUF 4            // quad-buffered tiles

typedef unsigned long long u64;

// ---- scratch (static __device__ — no allocation allowed) ----
__device__ float g_qk[HH * DD];
__device__ float g_ps[(size_t)BB * CBLK * HH * DD];
__device__ float g_pz[BB * CBLK * HH];
__device__ float g_s[(size_t)BB * HH * DD];
__device__ float g_pooled[BB * DD];

// ---- packed f32x2 helpers ----
__device__ __forceinline__ u64 ffma2(u64 a, u64 b, u64 c) {
    u64 d;
    asm("fma.rn.f32x2 %0, %1, %2, %3;" : "=l"(d) : "l"(a), "l"(b), "l"(c));
    return d;
}
__device__ __forceinline__ u64 pack2(float lo, float hi) {
    u64 d;
    asm("mov.b64 %0, {%1, %2};" : "=l"(d) : "f"(lo), "f"(hi));
    return d;
}
__device__ __forceinline__ float2 unpack2(u64 v) {
    float2 r;
    asm("mov.b64 {%0, %1}, %2;" : "=f"(r.x), "=f"(r.y) : "l"(v));
    return r;
}
__device__ __forceinline__ float ex2_approx(float v) {
    float r;
    asm("ex2.approx.f32 %0, %1;" : "=f"(r) : "f"(v));
    return r;
}

// ---- cp.async helpers ----
__device__ __forceinline__ void cpasync16(uint32_t saddr, const void* gaddr) {
    asm volatile("cp.async.cg.shared.global [%0], [%1], 16;" :: "r"(saddr), "l"(gaddr));
}
__device__ __forceinline__ void cpasync_commit() {
    asm volatile("cp.async.commit_group;");
}
__device__ __forceinline__ void cpasync_wait0() {
    asm volatile("cp.async.wait_group 0;");
}
__device__ __forceinline__ void cpasync_wait1() {
    asm volatile("cp.async.wait_group 1;");
}

// ---------------------------------------------------------------------------
// K0: qk[h][d] = (log2e/SCALE) * sum_j query[h][j] * Wk[h*64+j][d]
// ---------------------------------------------------------------------------
__global__ void k0_qk(const float* __restrict__ Wk, const float* __restrict__ query) {
    int gid = blockIdx.x * 256 + threadIdx.x;   // 16384 = H*D
    int h = gid >> 10;
    int d = gid & 1023;
    const float C = 0.125f * 1.4426950408889634f;
    float acc = 0.f;
#pragma unroll 8
    for (int j = 0; j < DKK; j++) {
        acc += __ldg(&query[h * DKK + j]) * __ldg(&Wk[(size_t)(h * DKK + j) * DD + d]);
    }
    g_qk[gid] = acc * C;
}

// ---------------------------------------------------------------------------
// A-chunk: scores for row p+2j (this warp's 4 heads) -> eo.
// Reduction: xor{8,16} on 4 head-sums (8 SHFL) -> SEL head by l>>3 ->
// xor{1,2,4} (3 SHFL) -> convergent ex2.approx -> predicated STS by q==0.
// ---------------------------------------------------------------------------
__device__ __forceinline__ void phaseA_j(const float* xt, u64 (*eo)[HH],
                                         const u64 qkr[4][16],
                                         int j, int l, int hg, int p) {
    int r = p + 2 * j;
    const ulonglong2* xr = (const ulonglong2*)(xt + (size_t)r * DD);
    u64 a0 = 0ull, a1 = 0ull, a2 = 0ull, a3 = 0ull;
#pragma unroll
    for (int i = 0; i < 8; i++) {
        ulonglong2 xv = xr[l + 32 * i];
        a0 = ffma2(xv.x, qkr[0][2 * i], a0);
        a1 = ffma2(xv.x, qkr[1][2 * i], a1);
        a2 = ffma2(xv.x, qkr[2][2 * i], a2);
        a3 = ffma2(xv.x, qkr[3][2 * i], a3);
        a0 = ffma2(xv.y, qkr[0][2 * i + 1], a0);
        a1 = ffma2(xv.y, qkr[1][2 * i + 1], a1);
        a2 = ffma2(xv.y, qkr[2][2 * i + 1], a2);
        a3 = ffma2(xv.y, qkr[3][2 * i + 1], a3);
    }
    float2 f0 = unpack2(a0), f1 = unpack2(a1), f2v = unpack2(a2), f3 = unpack2(a3);
    float s0 = f0.x + f0.y, s1 = f1.x + f1.y, s2 = f2v.x + f2v.y, s3 = f3.x + f3.y;

    // phase 1: reduce over lane bits 3,4 -> values depend only on l&7
#pragma unroll
    for (int m = 8; m <= 16; m <<= 1) {
        s0 += __shfl_xor_sync(0xffffffffu, s0, m);
        s1 += __shfl_xor_sync(0xffffffffu, s1, m);
        s2 += __shfl_xor_sync(0xffffffffu, s2, m);
        s3 += __shfl_xor_sync(0xffffffffu, s3, m);
    }
    // phase 2: lane group g = l>>3 takes head g, reduce over bits 0..2
    int g = l >> 3;
    float v = (g == 0) ? s0 : (g == 1) ? s1 : (g == 2) ? s2 : s3;
    v += __shfl_xor_sync(0xffffffffu, v, 1);
    v += __shfl_xor_sync(0xffffffffu, v, 2);
    v += __shfl_xor_sync(0xffffffffu, v, 4);

    float e = ex2_approx(v);                 // convergent, all lanes
    if ((l & 7) == 0) eo[r][4 * hg + g] = pack2(e, e);
}

// ---------------------------------------------------------------------------
// B-chunk: weighted accumulation of one row (32 FFMA2, e via LDS.128 pairs)
// ---------------------------------------------------------------------------
__device__ __forceinline__ void phaseB_row(const float* xt, const u64 (*eb)[HH],
                                           u64 acc[HH][2], int r, int t) {
    ulonglong2 xv = ((const ulonglong2*)(xt + (size_t)r * DD))[t];
    const ulonglong2* ep = (const ulonglong2*)eb[r];
#pragma unroll
    for (int hh = 0; hh < 8; hh++) {
        ulonglong2 e2 = ep[hh];              // uniform -> LDS.128 broadcast
        acc[2 * hh][0]     = ffma2(e2.x, xv.x, acc[2 * hh][0]);
        acc[2 * hh][1]     = ffma2(e2.x, xv.y, acc[2 * hh][1]);
        acc[2 * hh + 1][0] = ffma2(e2.y, xv.x, acc[2 * hh + 1][0]);
        acc[2 * hh + 1][1] = ffma2(e2.y, xv.y, acc[2 * hh + 1][1]);
    }
}

// ---------------------------------------------------------------------------
// FUSED v5 — skewed pipeline + A/B interleave + convergent ex2 reduction.
// ---------------------------------------------------------------------------
__global__ void __launch_bounds__(256) fused_attn(const float* __restrict__ x) {
    extern __shared__ __align__(16) float xs[];     // XBUF * TR * DD floats (128 KB)
    __shared__ __align__(16) u64 es[2][TR][HH];     // {e,e}-duplicated, parity buffered

    int c = blockIdx.x;
    int b = blockIdx.y;
    int t = threadIdx.x;
    int w = t >> 5, l = t & 31;
    int hg = w & 3, p = w >> 2;

    u64 qkr[4][16];
#pragma unroll
    for (int h = 0; h < 4; h++) {
        const ulonglong2* q = (const ulonglong2*)&g_qk[(4 * hg + h) * DD + 4 * l];
#pragma unroll
        for (int i = 0; i < 8; i++) {
            ulonglong2 v = q[32 * i];
            qkr[h][2 * i] = v.x;
            qkr[h][2 * i + 1] = v.y;
        }
    }

    u64 acc[HH][2];
#pragma unroll
    for (int h = 0; h < HH; h++) { acc[h][0] = 0ull; acc[h][1] = 0ull; }
    float zacc = 0.f;

    int n0 = c * CROWS;
    int nrows = (c == CBLK - 1) ? (NN - (CBLK - 1) * CROWS) : CROWS;
    int ntiles = nrows / TR;                       // 57 or 56

    const char* xg = (const char*)(x + ((size_t)b * NN + n0) * DD);
    const size_t TILEB = (size_t)TR * DD * 4;      // 32768 bytes

    // prologue: prefetch tiles 0 and 1
#pragma unroll
    for (int pf = 0; pf < 2; pf++) {
        uint32_t sb = (uint32_t)__cvta_generic_to_shared(xs + pf * TR * DD);
        const char* g = xg + (size_t)pf * TILEB;
#pragma unroll
        for (int k2 = 0; k2 < 8; k2++)
            cpasync16(sb + t * 16 + k2 * 4096, g + t * 16 + k2 * 4096);
        cpasync_commit();
    }

    // ---- peeled tile 0: A only ----
    {
        if (1 < ntiles) cpasync_wait1(); else cpasync_wait0();
        __syncthreads();
        if (2 < ntiles) {
            uint32_t sb = (uint32_t)__cvta_generic_to_shared(xs + 2 * TR * DD);
            const char* g = xg + 2 * TILEB;
#pragma unroll
            for (int k2 = 0; k2 < 8; k2++)
                cpasync16(sb + t * 16 + k2 * 4096, g + t * 16 + k2 * 4096);
            cpasync_commit();
        }
        const float* xt = xs;                      // buf 0
#pragma unroll
        for (int j = 0; j < 4; j++) phaseA_j(xt, es[0], qkr, j, l, hg, p);
    }

    // ---- main loop: interleaved A(tile) + B(tile-1) ----
    for (int tile = 1; tile < ntiles; tile++) {
        if (tile + 1 < ntiles) cpasync_wait1();
        else                   cpasync_wait0();
        __syncthreads();   // xs[tile&3] resident; es[(tile-1)&1] complete

        if (tile + 2 < ntiles) {
            uint32_t sb = (uint32_t)__cvta_generic_to_shared(
                xs + ((tile + 2) & 3) * TR * DD);
            const char* g = xg + (size_t)(tile + 2) * TILEB;
#pragma unroll
            for (int k2 = 0; k2 < 8; k2++)
                cpasync16(sb + t * 16 + k2 * 4096, g + t * 16 + k2 * 4096);
            cpasync_commit();
        }

        const float* xta = xs + (tile & 3) * TR * DD;
        const float* xtb = xs + ((tile - 1) & 3) * TR * DD;
        u64 (*eo)[HH] = es[tile & 1];
        const u64 (*eb)[HH] = (const u64 (*)[HH])es[(tile - 1) & 1];

#pragma unroll
        for (int j = 0; j < 4; j++) {
            phaseA_j(xta, eo, qkr, j, l, hg, p);     // independent of B below
            phaseB_row(xtb, eb, acc, 2 * j, t);
            phaseB_row(xtb, eb, acc, 2 * j + 1, t);
        }
        if (t < HH) {
#pragma unroll
            for (int r = 0; r < TR; r++) zacc += unpack2(eb[r][t]).x;
        }
    }

    // ---- peeled final B(ntiles-1) ----
    __syncthreads();
    {
        const float* xtb = xs + ((ntiles - 1) & 3) * TR * DD;
        const u64 (*eb)[HH] = (const u64 (*)[HH])es[(ntiles - 1) & 1];
#pragma unroll
        for (int r = 0; r < TR; r++) phaseB_row(xtb, eb, acc, r, t);
        if (t < HH) {
#pragma unroll
            for (int r = 0; r < TR; r++) zacc += unpack2(eb[r][t]).x;
        }
    }

    // ---- epilogue: coalesced float4 partial writes ----
    size_t base = (size_t)(b * CBLK + c) * HH * DD;
#pragma unroll
    for (int h = 0; h < HH; h++) {
        float2 v0 = unpack2(acc[h][0]);
        float2 v1 = unpack2(acc[h][1]);
        *(float4*)&g_ps[base + (size_t)h * DD + 4 * t] =
            make_float4(v0.x, v0.y, v1.x, v1.y);
    }
    if (t < HH) g_pz[(b * CBLK + c) * HH + t] = zacc;
}

// ---------------------------------------------------------------------------
// K3: combine partials + normalize: s[b][h][d] = sum_c ps / z[b][h]
// ---------------------------------------------------------------------------
__global__ void k3_combine() {
    size_t gid = (size_t)blockIdx.x * 256 + threadIdx.x;   // B*H*D = 262144
    int b = (int)(gid >> 14);
    int rem = (int)(gid & 16383);
    int h = rem >> 10;
    float z = 0.f;
#pragma unroll
    for (int c = 0; c < CBLK; c++) z += g_pz[(b * CBLK + c) * HH + h];
    float sum = 0.f;
#pragma unroll
    for (int c = 0; c < CBLK; c++) {
        sum += g_ps[(size_t)(b * CBLK + c) * HH * DD + rem];
    }
    g_s[gid] = sum / z;
}

// ---------------------------------------------------------------------------
// K4: pooled[b][o] = Wv[o,:] . s[b][o>>6][:]
// ---------------------------------------------------------------------------
__global__ void __launch_bounds__(256) k4_pooled(const float* __restrict__ Wv) {
    int w = threadIdx.x >> 5, l = threadIdx.x & 31;
    int o = blockIdx.x * 8 + w;
    int b = blockIdx.y;
    int h = o >> 6;
    const float4* wr = (const float4*)(Wv + (size_t)o * DD);
    const float4* sr = (const float4*)(g_s + (size_t)(b * HH + h) * DD);
    float acc = 0.f;
#pragma unroll
    for (int i = 0; i < 8; i++) {
        float4 a = __ldg(&wr[l + 32 * i]);
        float4 s4 = sr[l + 32 * i];
        acc += a.x * s4.x + a.y * s4.y + a.z * s4.z + a.w * s4.w;
    }
    acc += __shfl_xor_sync(0xffffffffu, acc, 16);
    acc += __shfl_xor_sync(0xffffffffu, acc, 8);
    acc += __shfl_xor_sync(0xffffffffu, acc, 4);
    acc += __shfl_xor_sync(0xffffffffu, acc, 2);
    acc += __shfl_xor_sync(0xffffffffu, acc, 1);
    if (l == 0) g_pooled[b * DD + o] = acc;
}

// ---------------------------------------------------------------------------
// K5: out[b][i] = Wout[i,:] . pooled[b,:] + bout[i]
// ---------------------------------------------------------------------------
__global__ void __launch_bounds__(256) k5_out(const float* __restrict__ Wout,
                                              const float* __restrict__ bout,
                                              float* __restrict__ out) {
    int w = threadIdx.x >> 5, l = threadIdx.x & 31;
    int i = blockIdx.x * 8 + w;
    int b = blockIdx.y;
    const float4* wr = (const float4*)(Wout + (size_t)i * DD);
    const float4* pr = (const float4*)(g_pooled + (size_t)b * DD);
    float acc = 0.f;
#pragma unroll
    for (int k = 0; k < 8; k++) {
        float4 a = __ldg(&wr[l + 32 * k]);
        float4 p4 = pr[l + 32 * k];
        acc += a.x * p4.x + a.y * p4.y + a.z * p4.z + a.w * p4.w;
    }
    acc += __shfl_xor_sync(0xffffffffu, acc, 16);
    acc += __shfl_xor_sync(0xffffffffu, acc, 8);
    acc += __shfl_xor_sync(0xffffffffu, acc, 4);
    acc += __shfl_xor_sync(0xffffffffu, acc, 2);
    acc += __shfl_xor_sync(0xffffffffu, acc, 1);
    if (l == 0) out[b * DD + i] = acc + __ldg(&bout[i]);
}

// ---------------------------------------------------------------------------
extern "C" void kernel_launch(void* const* d_in, const int* in_sizes, int n_in,
                              void* d_out, int out_size) {
    const float* x     = (const float*)d_in[0];  // (16,4096,1024)
    const float* Wk    = (const float*)d_in[1];  // (1024,1024)
    const float* Wv    = (const float*)d_in[2];  // (1024,1024)
    const float* query = (const float*)d_in[3];  // (16,1,64)
    const float* Wout  = (const float*)d_in[4];  // (1024,1024)
    const float* bout  = (const float*)d_in[5];  // (1024,)
    float* out = (float*)d_out;                  // (16,1024)

    const int XS_BYTES = XBUF * TR * DD * 4;     // 131072
    cudaFuncSetAttribute(fused_attn,
                         cudaFuncAttributeMaxDynamicSharedMemorySize, XS_BYTES);

    k0_qk<<<HH * DD / 256, 256>>>(Wk, query);
    fused_attn<<<dim3(CBLK, BB), 256, XS_BYTES>>>(x);
    k3_combine<<<BB * HH * DD / 256, 256>>>();
    k4_pooled<<<dim3(DD / 8, BB), 256>>>(Wv);
    k5_out<<<dim3(DD / 8, BB), 256>>>(Wout, bout, out);
}

// round 16
// speedup vs baseline: 5.5154x; 1.0669x over previous
#include <cuda_runtime.h>
#include <cstdint>

#define BB 16
#define NN 4096
#define DD 1024
#define HH 16
#define DKK 64
#define CBLK 9            // row-chunks per batch -> 144 blocks ~= 1 wave
#define CROWS 456         // rows per chunk (c<8); last gets 448; both /8
#define TR 8              // tile rows (32 KB/tile)
#define XBUF 4            // quad-buffered tiles
#define EBUF 4            // es depth (skew tolerance < 4 tiles)

typedef unsigned long long u64;

// ---- scratch (static __device__ — no allocation allowed) ----
__device__ float g_qk[HH * DD];
__device__ float g_ps[(size_t)BB * CBLK * HH * DD];
__device__ float g_pz[BB * CBLK * HH];
__device__ float g_s[(size_t)BB * HH * DD];
__device__ float g_pooled[BB * DD];

// ---- packed f32x2 helpers ----
__device__ __forceinline__ u64 ffma2(u64 a, u64 b, u64 c) {
    u64 d;
    asm("fma.rn.f32x2 %0, %1, %2, %3;" : "=l"(d) : "l"(a), "l"(b), "l"(c));
    return d;
}
__device__ __forceinline__ u64 pack2(float lo, float hi) {
    u64 d;
    asm("mov.b64 %0, {%1, %2};" : "=l"(d) : "f"(lo), "f"(hi));
    return d;
}
__device__ __forceinline__ float2 unpack2(u64 v) {
    float2 r;
    asm("mov.b64 {%0, %1}, %2;" : "=f"(r.x), "=f"(r.y) : "l"(v));
    return r;
}
__device__ __forceinline__ float ex2_approx(float v) {
    float r;
    asm("ex2.approx.f32 %0, %1;" : "=f"(r) : "f"(v));
    return r;
}

// ---- cp.async helpers ----
__device__ __forceinline__ void cpasync16(uint32_t saddr, const void* gaddr) {
    asm volatile("cp.async.cg.shared.global [%0], [%1], 16;" :: "r"(saddr), "l"(gaddr));
}
__device__ __forceinline__ void cpasync_commit() {
    asm volatile("cp.async.commit_group;");
}
__device__ __forceinline__ void cpasync_wait0() {
    asm volatile("cp.async.wait_group 0;");
}
__device__ __forceinline__ void cpasync_wait1() {
    asm volatile("cp.async.wait_group 1;");
}

// ---------------------------------------------------------------------------
// K0: qk[h][d] = (log2e/SCALE) * sum_j query[h][j] * Wk[h*64+j][d]
// ---------------------------------------------------------------------------
__global__ void k0_qk(const float* __restrict__ Wk, const float* __restrict__ query) {
    int gid = blockIdx.x * 256 + threadIdx.x;   // 16384 = H*D
    int h = gid >> 10;
    int d = gid & 1023;
    const float C = 0.125f * 1.4426950408889634f;
    float acc = 0.f;
#pragma unroll 8
    for (int j = 0; j < DKK; j++) {
        acc += __ldg(&query[h * DKK + j]) * __ldg(&Wk[(size_t)(h * DKK + j) * DD + d]);
    }
    g_qk[gid] = acc * C;
}

// ---------------------------------------------------------------------------
// A-chunk: scores for row p+2j (this warp's 4 heads) -> eo.
// xor{8,16} on 4 head-sums -> SEL head by l>>3 -> xor{1,2,4} -> convergent
// ex2.approx -> predicated STS by (l&7)==0.
// ---------------------------------------------------------------------------
__device__ __forceinline__ void phaseA_j(const float* xt, u64 (*eo)[HH],
                                         const u64 qkr[4][16],
                                         int j, int l, int hg, int p) {
    int r = p + 2 * j;
    const ulonglong2* xr = (const ulonglong2*)(xt + (size_t)r * DD);
    u64 a0 = 0ull, a1 = 0ull, a2 = 0ull, a3 = 0ull;
#pragma unroll
    for (int i = 0; i < 8; i++) {
        ulonglong2 xv = xr[l + 32 * i];
        a0 = ffma2(xv.x, qkr[0][2 * i], a0);
        a1 = ffma2(xv.x, qkr[1][2 * i], a1);
        a2 = ffma2(xv.x, qkr[2][2 * i], a2);
        a3 = ffma2(xv.x, qkr[3][2 * i], a3);
        a0 = ffma2(xv.y, qkr[0][2 * i + 1], a0);
        a1 = ffma2(xv.y, qkr[1][2 * i + 1], a1);
        a2 = ffma2(xv.y, qkr[2][2 * i + 1], a2);
        a3 = ffma2(xv.y, qkr[3][2 * i + 1], a3);
    }
    float2 f0 = unpack2(a0), f1 = unpack2(a1), f2v = unpack2(a2), f3 = unpack2(a3);
    float s0 = f0.x + f0.y, s1 = f1.x + f1.y, s2 = f2v.x + f2v.y, s3 = f3.x + f3.y;
#pragma unroll
    for (int m = 8; m <= 16; m <<= 1) {
        s0 += __shfl_xor_sync(0xffffffffu, s0, m);
        s1 += __shfl_xor_sync(0xffffffffu, s1, m);
        s2 += __shfl_xor_sync(0xffffffffu, s2, m);
        s3 += __shfl_xor_sync(0xffffffffu, s3, m);
    }
    int g = l >> 3;
    float v = (g == 0) ? s0 : (g == 1) ? s1 : (g == 2) ? s2 : s3;
    v += __shfl_xor_sync(0xffffffffu, v, 1);
    v += __shfl_xor_sync(0xffffffffu, v, 2);
    v += __shfl_xor_sync(0xffffffffu, v, 4);

    float e = ex2_approx(v);                 // convergent, all lanes
    if ((l & 7) == 0) eo[r][4 * hg + g] = pack2(e, e);
}

// ---------------------------------------------------------------------------
// B-chunk: weighted accumulation of one row. NOTE: each thread reads EXACTLY
// its own cp.async slice (r*4096 + t*16) — per-thread self-coherent, which is
// what legalizes the second prefetch commit per interval without a barrier.
// ---------------------------------------------------------------------------
__device__ __forceinline__ void phaseB_row(const float* xt, const u64 (*eb)[HH],
                                           u64 acc[HH][2], int r, int t) {
    ulonglong2 xv = ((const ulonglong2*)(xt + (size_t)r * DD))[t];
    const ulonglong2* ep = (const ulonglong2*)eb[r];
#pragma unroll
    for (int hh = 0; hh < 8; hh++) {
        ulonglong2 e2 = ep[hh];              // uniform -> LDS.128 broadcast
        acc[2 * hh][0]     = ffma2(e2.x, xv.x, acc[2 * hh][0]);
        acc[2 * hh][1]     = ffma2(e2.x, xv.y, acc[2 * hh][1]);
        acc[2 * hh + 1][0] = ffma2(e2.y, xv.x, acc[2 * hh + 1][0]);
        acc[2 * hh + 1][1] = ffma2(e2.y, xv.y, acc[2 * hh + 1][1]);
    }
}

// ---------------------------------------------------------------------------
// FUSED v6 — 2-tile barrier intervals.
// interval (T odd): wait0; sync  [xs T, T+1 resident across ALL warps]
//   commit P(T+2)           (buffer (T+2)&3: all readers finished pre-barrier)
//   A(T) -> es[T&3] ; B(T-1) <- es[(T-1)&3]
//   commit P(T+3)           (buffer (T-1)&3: own-thread B(T-1) done; A(T-1)
//                            finished pre-barrier)
//   A(T+1) -> es[(T+1)&3] ; B(T) <- es[T&3]
// es depth 4 bounds intra-interval producer/consumer skew (diff <= 2).
// ---------------------------------------------------------------------------
__global__ void __launch_bounds__(256) fused_attn(const float* __restrict__ x) {
    extern __shared__ __align__(16) float xs[];     // XBUF * TR * DD floats (128 KB)
    __shared__ __align__(16) u64 es[EBUF][TR][HH];  // {e,e}-duplicated, 4 KB

    int c = blockIdx.x;
    int b = blockIdx.y;
    int t = threadIdx.x;
    int w = t >> 5, l = t & 31;
    int hg = w & 3, p = w >> 2;

    u64 qkr[4][16];
#pragma unroll
    for (int h = 0; h < 4; h++) {
        const ulonglong2* q = (const ulonglong2*)&g_qk[(4 * hg + h) * DD + 4 * l];
#pragma unroll
        for (int i = 0; i < 8; i++) {
            ulonglong2 v = q[32 * i];
            qkr[h][2 * i] = v.x;
            qkr[h][2 * i + 1] = v.y;
        }
    }

    u64 acc[HH][2];
#pragma unroll
    for (int h = 0; h < HH; h++) { acc[h][0] = 0ull; acc[h][1] = 0ull; }
    float zacc = 0.f;

    int n0 = c * CROWS;
    int nrows = (c == CBLK - 1) ? (NN - (CBLK - 1) * CROWS) : CROWS;
    int ntiles = nrows / TR;                       // 57 or 56

    const char* xg = (const char*)(x + ((size_t)b * NN + n0) * DD);
    const size_t TILEB = (size_t)TR * DD * 4;      // 32768 bytes

    // prologue: prefetch tiles 0 and 1
#pragma unroll
    for (int pf = 0; pf < 2; pf++) {
        uint32_t sb = (uint32_t)__cvta_generic_to_shared(xs + pf * TR * DD);
        const char* g = xg + (size_t)pf * TILEB;
#pragma unroll
        for (int k2 = 0; k2 < 8; k2++)
            cpasync16(sb + t * 16 + k2 * 4096, g + t * 16 + k2 * 4096);
        cpasync_commit();
    }

    // ---- pre-interval: A(0) only ----
    cpasync_wait1();                 // xs[0] resident (own); xs[1] may fly
    __syncthreads();                 // cross-warp visibility of xs[0]
    if (2 < ntiles) {
        uint32_t sb = (uint32_t)__cvta_generic_to_shared(xs + 2 * TR * DD);
        const char* g = xg + 2 * TILEB;
#pragma unroll
        for (int k2 = 0; k2 < 8; k2++)
            cpasync16(sb + t * 16 + k2 * 4096, g + t * 16 + k2 * 4096);
        cpasync_commit();
    }
#pragma unroll
    for (int j = 0; j < 4; j++) phaseA_j(xs, es[0], qkr, j, l, hg, p);

    // ---- main loop: 2-tile intervals, T odd ----
    for (int T = 1; T < ntiles; T += 2) {
        cpasync_wait0();             // all own groups done (xs[T], xs[T+1])
        __syncthreads();             // cross-warp: both tiles fully resident

        // prefetch T+2 (buffer (T+2)&3 — all prior readers pre-barrier)
        if (T + 2 < ntiles) {
            uint32_t sb = (uint32_t)__cvta_generic_to_shared(
                xs + ((T + 2) & 3) * TR * DD);
            const char* g = xg + (size_t)(T + 2) * TILEB;
#pragma unroll
            for (int k2 = 0; k2 < 8; k2++)
                cpasync16(sb + t * 16 + k2 * 4096, g + t * 16 + k2 * 4096);
            cpasync_commit();
        }

        {   // A(T) + B(T-1) interleaved
            const float* xta = xs + (T & 3) * TR * DD;
            const float* xtb = xs + ((T - 1) & 3) * TR * DD;
            u64 (*eo)[HH] = es[T & 3];
            const u64 (*eb)[HH] = (const u64 (*)[HH])es[(T - 1) & 3];
#pragma unroll
            for (int j = 0; j < 4; j++) {
                phaseA_j(xta, eo, qkr, j, l, hg, p);
                phaseB_row(xtb, eb, acc, 2 * j, t);
                phaseB_row(xtb, eb, acc, 2 * j + 1, t);
            }
            if (t < HH) {
#pragma unroll
                for (int r = 0; r < TR; r++) zacc += unpack2(eb[r][t]).x;
            }
        }

        // prefetch T+3 into buffer (T-1)&3: own-thread B(T-1) reads done
        if (T + 3 < ntiles) {
            uint32_t sb = (uint32_t)__cvta_generic_to_shared(
                xs + ((T + 3) & 3) * TR * DD);
            const char* g = xg + (size_t)(T + 3) * TILEB;
#pragma unroll
            for (int k2 = 0; k2 < 8; k2++)
                cpasync16(sb + t * 16 + k2 * 4096, g + t * 16 + k2 * 4096);
            cpasync_commit();
        }

        if (T + 1 < ntiles) {   // A(T+1) + B(T) interleaved
            const float* xta = xs + ((T + 1) & 3) * TR * DD;
            const float* xtb = xs + (T & 3) * TR * DD;
            u64 (*eo)[HH] = es[(T + 1) & 3];
            const u64 (*eb)[HH] = (const u64 (*)[HH])es[T & 3];
#pragma unroll
            for (int j = 0; j < 4; j++) {
                phaseA_j(xta, eo, qkr, j, l, hg, p);
                phaseB_row(xtb, eb, acc, 2 * j, t);
                phaseB_row(xtb, eb, acc, 2 * j + 1, t);
            }
            if (t < HH) {
#pragma unroll
                for (int r = 0; r < TR; r++) zacc += unpack2(eb[r][t]).x;
            }
        }
    }

    // ---- peeled final B(ntiles-1) ----
    __syncthreads();                 // order last A-writes vs cross-warp reads
    {
        const float* xtb = xs + ((ntiles - 1) & 3) * TR * DD;
        const u64 (*eb)[HH] = (const u64 (*)[HH])es[(ntiles - 1) & 3];
#pragma unroll
        for (int r = 0; r < TR; r++) phaseB_row(xtb, eb, acc, r, t);
        if (t < HH) {
#pragma unroll
            for (int r = 0; r < TR; r++) zacc += unpack2(eb[r][t]).x;
        }
    }

    // ---- epilogue: coalesced float4 partial writes ----
    size_t base = (size_t)(b * CBLK + c) * HH * DD;
#pragma unroll
    for (int h = 0; h < HH; h++) {
        float2 v0 = unpack2(acc[h][0]);
        float2 v1 = unpack2(acc[h][1]);
        *(float4*)&g_ps[base + (size_t)h * DD + 4 * t] =
            make_float4(v0.x, v0.y, v1.x, v1.y);
    }
    if (t < HH) g_pz[(b * CBLK + c) * HH + t] = zacc;
}

// ---------------------------------------------------------------------------
// K3: combine partials + normalize (float4): s[b][h][d] = sum_c ps / z[b][h]
// ---------------------------------------------------------------------------
__global__ void k3_combine() {
    int gid = blockIdx.x * 256 + threadIdx.x;      // 65536 float4s
    int b = gid >> 12;                             // 4096 float4 per batch
    int rem4 = gid & 4095;                         // float4 idx within (h,d)
    int h = rem4 >> 8;                             // 256 float4 per head
    float z = 0.f;
#pragma unroll
    for (int c = 0; c < CBLK; c++) z += g_pz[(b * CBLK + c) * HH + h];
    float4 s = make_float4(0.f, 0.f, 0.f, 0.f);
#pragma unroll
    for (int c = 0; c < CBLK; c++) {
        float4 v = ((const float4*)g_ps)[(size_t)(b * CBLK + c) * (HH * DD / 4) + rem4];
        s.x += v.x; s.y += v.y; s.z += v.z; s.w += v.w;
    }
    float inv = 1.0f / z;
    s.x *= inv; s.y *= inv; s.z *= inv; s.w *= inv;
    ((float4*)g_s)[(size_t)b * (HH * DD / 4) + rem4] = s;
}

// ---------------------------------------------------------------------------
// K4: pooled[b][o] = Wv[o,:] . s[b][o>>6][:]  — 4 batches per warp (Wv row
// loaded once per 4 b), 512 blocks.
// ---------------------------------------------------------------------------
__global__ void __launch_bounds__(256) k4_pooled(const float* __restrict__ Wv) {
    int w = threadIdx.x >> 5, l = threadIdx.x & 31;
    int o = blockIdx.x * 8 + w;
    int b0 = blockIdx.y * 4;
    int h = o >> 6;
    const float4* wr = (const float4*)(Wv + (size_t)o * DD);
    float a0 = 0.f, a1 = 0.f, a2 = 0.f, a3 = 0.f;
#pragma unroll
    for (int i = 0; i < 8; i++) {
        float4 a = __ldg(&wr[l + 32 * i]);
        const float4* s0 = (const float4*)(g_s + (size_t)((b0 + 0) * HH + h) * DD) + l + 32 * i;
        const float4* s1 = (const float4*)(g_s + (size_t)((b0 + 1) * HH + h) * DD) + l + 32 * i;
        const float4* s2 = (const float4*)(g_s + (size_t)((b0 + 2) * HH + h) * DD) + l + 32 * i;
        const float4* s3 = (const float4*)(g_s + (size_t)((b0 + 3) * HH + h) * DD) + l + 32 * i;
        float4 v0 = *s0, v1 = *s1, v2 = *s2, v3 = *s3;
        a0 += a.x * v0.x + a.y * v0.y + a.z * v0.z + a.w * v0.w;
        a1 += a.x * v1.x + a.y * v1.y + a.z * v1.z + a.w * v1.w;
        a2 += a.x * v2.x + a.y * v2.y + a.z * v2.z + a.w * v2.w;
        a3 += a.x * v3.x + a.y * v3.y + a.z * v3.z + a.w * v3.w;
    }
#pragma unroll
    for (int m = 16; m > 0; m >>= 1) {
        a0 += __shfl_xor_sync(0xffffffffu, a0, m);
        a1 += __shfl_xor_sync(0xffffffffu, a1, m);
        a2 += __shfl_xor_sync(0xffffffffu, a2, m);
        a3 += __shfl_xor_sync(0xffffffffu, a3, m);
    }
    if (l == 0) {
        g_pooled[(b0 + 0) * DD + o] = a0;
        g_pooled[(b0 + 1) * DD + o] = a1;
        g_pooled[(b0 + 2) * DD + o] = a2;
        g_pooled[(b0 + 3) * DD + o] = a3;
    }
}

// ---------------------------------------------------------------------------
// K5: out[b][i] = Wout[i,:] . pooled[b,:] + bout[i] — 4 batches per warp.
// ---------------------------------------------------------------------------
__global__ void __launch_bounds__(256) k5_out(const float* __restrict__ Wout,
                                              const float* __restrict__ bout,
                                              float* __restrict__ out) {
    int w = threadIdx.x >> 5, l = threadIdx.x & 31;
    int i = blockIdx.x * 8 + w;
    int b0 = blockIdx.y * 4;
    const float4* wr = (const float4*)(Wout + (size_t)i * DD);
    float a0 = 0.f, a1 = 0.f, a2 = 0.f, a3 = 0.f;
#pragma unroll
    for (int k = 0; k < 8; k++) {
        float4 a = __ldg(&wr[l + 32 * k]);
        const float4* p0 = (const float4*)(g_pooled + (size_t)(b0 + 0) * DD) + l + 32 * k;
        const float4* p1 = (const float4*)(g_pooled + (size_t)(b0 + 1) * DD) + l + 32 * k;
        const float4* p2 = (const float4*)(g_pooled + (size_t)(b0 + 2) * DD) + l + 32 * k;
        const float4* p3 = (const float4*)(g_pooled + (size_t)(b0 + 3) * DD) + l + 32 * k;
        float4 v0 = *p0, v1 = *p1, v2 = *p2, v3 = *p3;
        a0 += a.x * v0.x + a.y * v0.y + a.z * v0.z + a.w * v0.w;
        a1 += a.x * v1.x + a.y * v1.y + a.z * v1.z + a.w * v1.w;
        a2 += a.x * v2.x + a.y * v2.y + a.z * v2.z + a.w * v2.w;
        a3 += a.x * v3.x + a.y * v3.y + a.z * v3.z + a.w * v3.w;
    }
#pragma unroll
    for (int m = 16; m > 0; m >>= 1) {
        a0 += __shfl_xor_sync(0xffffffffu, a0, m);
        a1 += __shfl_xor_sync(0xffffffffu, a1, m);
        a2 += __shfl_xor_sync(0xffffffffu, a2, m);
        a3 += __shfl_xor_sync(0xffffffffu, a3, m);
    }
    if (l == 0) {
        float bo = __ldg(&bout[i]);
        out[(b0 + 0) * DD + i] = a0 + bo;
        out[(b0 + 1) * DD + i] = a1 + bo;
        out[(b0 + 2) * DD + i] = a2 + bo;
        out[(b0 + 3) * DD + i] = a3 + bo;
    }
}

// ---------------------------------------------------------------------------
extern "C" void kernel_launch(void* const* d_in, const int* in_sizes, int n_in,
                              void* d_out, int out_size) {
    const float* x     = (const float*)d_in[0];  // (16,4096,1024)
    const float* Wk    = (const float*)d_in[1];  // (1024,1024)
    const float* Wv    = (const float*)d_in[2];  // (1024,1024)
    const float* query = (const float*)d_in[3];  // (16,1,64)
    const float* Wout  = (const float*)d_in[4];  // (1024,1024)
    const float* bout  = (const float*)d_in[5];  // (1024,)
    float* out = (float*)d_out;                  // (16,1024)

    const int XS_BYTES = XBUF * TR * DD * 4;     // 131072
    cudaFuncSetAttribute(fused_attn,
                         cudaFuncAttributeMaxDynamicSharedMemorySize, XS_BYTES);

    k0_qk<<<HH * DD / 256, 256>>>(Wk, query);
    fused_attn<<<dim3(CBLK, BB), 256, XS_BYTES>>>(x);
    k3_combine<<<BB * HH * DD / 4 / 256, 256>>>();
    k4_pooled<<<dim3(DD / 8, BB / 4), 256>>>(Wv);
    k5_out<<<dim3(DD / 8, BB / 4), 256>>>(Wout, bout, out);
}